// round 7
// baseline (speedup 1.0000x reference)
#include <cuda_runtime.h>

#define NN   100000
#define DEG  16
#define EE   (NN * DEG)
#define TPB  128

// Scratch (no allocations allowed): ping-pong node features, per-node xW1, aggregates.
__device__ float g_bufA[(size_t)NN * 32];
__device__ float g_bufB[(size_t)NN * 32];
__device__ float g_xw1[(size_t)NN * 64];
__device__ float g_aggr[(size_t)NN * 32];
__device__ int   g_src[(size_t)EE];

__device__ __forceinline__ float relu_(float v) { return fmaxf(v, 0.0f); }

// ---------------------------------------------------------------------------
// Kernel 0: normalize edge_index row 0 (src) to int32, regardless of whether
// the device buffer is int32 or int64. For int64 little-endian values < 2^31,
// every odd 32-bit word is zero; with int32 data those words are random node
// ids (P(zero) = 1e-5 each), so 64 consecutive odd words all-zero decides it.
// Each block computes the predicate independently (deterministic, cheap).
// ---------------------------------------------------------------------------
__global__ __launch_bounds__(TPB) void k_convert(const int* __restrict__ ei_raw, int E) {
    __shared__ int s_is64;
    if (threadIdx.x == 0) {
        int allz = 1;
        for (int k = 0; k < 64; k++) allz &= (ei_raw[2 * k + 1] == 0);
        s_is64 = allz;
    }
    __syncthreads();
    int is64 = s_is64;
    int e = blockIdx.x * TPB + threadIdx.x;
    if (e < E) g_src[e] = is64 ? ei_raw[2 * e] : ei_raw[e];
}

// ---------------------------------------------------------------------------
// Kernel 1: g_xw1[n][j] = b1_1[j] + sum_{k<32} x[n][k] * w1_1[j][k]
// (the x-part of the edge MLP's first layer, hoisted out of the edge loop).
// Only needed for the FIRST iteration; later iterations fuse this into k_update.
// ---------------------------------------------------------------------------
__global__ __launch_bounds__(TPB) void k_xw1(const float* __restrict__ x,
                                             const float* __restrict__ w11,
                                             const float* __restrict__ b11,
                                             int N) {
    __shared__ __align__(16) float sW[64 * 40];
    __shared__ float sB[64];
    for (int i = threadIdx.x; i < 64 * 40; i += TPB) sW[i] = w11[i];
    if (threadIdx.x < 64) sB[threadIdx.x] = b11[threadIdx.x];
    __syncthreads();

    int n = blockIdx.x * TPB + threadIdx.x;
    if (n >= N) return;

    float xr[32];
    const float4* xp = (const float4*)(x + (size_t)n * 32);
#pragma unroll
    for (int t = 0; t < 8; t++) {
        float4 v = xp[t];
        xr[4*t+0] = v.x; xr[4*t+1] = v.y; xr[4*t+2] = v.z; xr[4*t+3] = v.w;
    }

    float4* op = (float4*)(g_xw1 + (size_t)n * 64);
    for (int j = 0; j < 64; j += 4) {
        float a0 = sB[j+0], a1 = sB[j+1], a2 = sB[j+2], a3 = sB[j+3];
        // row stride 40 floats = 160 bytes -> float4-aligned
        const float4* w0 = (const float4*)(sW + (j+0) * 40);
        const float4* w1 = (const float4*)(sW + (j+1) * 40);
        const float4* w2 = (const float4*)(sW + (j+2) * 40);
        const float4* w3 = (const float4*)(sW + (j+3) * 40);
#pragma unroll
        for (int t = 0; t < 8; t++) {
            float h0 = xr[4*t+0], h1 = xr[4*t+1], h2 = xr[4*t+2], h3 = xr[4*t+3];
            float4 p;
            p = w0[t]; a0 += h0*p.x + h1*p.y + h2*p.z + h3*p.w;
            p = w1[t]; a1 += h0*p.x + h1*p.y + h2*p.z + h3*p.w;
            p = w2[t]; a2 += h0*p.x + h1*p.y + h2*p.z + h3*p.w;
            p = w3[t]; a3 += h0*p.x + h1*p.y + h2*p.z + h3*p.w;
        }
        op[j >> 2] = make_float4(a0, a1, a2, a3);
    }
}

// ---------------------------------------------------------------------------
// Kernel 2: per-node edge MLP + max aggregation.
// dst = repeat(arange(N), DEG): node n owns edges [n*DEG, (n+1)*DEG).
// h = relu(g_xw1[src] + edge_attr @ Wea)  (64)
// msg = relu(h @ w1_2^T + b1_2)           (32)
// aggr[n] = max over the 16 messages.
// ---------------------------------------------------------------------------
__global__ __launch_bounds__(TPB, 3) void k_edge(const float* __restrict__ eattr,
                                                 const float* __restrict__ w11,
                                                 const float* __restrict__ w12,
                                                 const float* __restrict__ b12,
                                                 int N) {
    __shared__ __align__(16) float sWea[8 * 64];   // sWea[a*64+i] = w11[i*40 + 32 + a]
    __shared__ __align__(16) float sW12[32 * 64];
    __shared__ float sB12[32];
    for (int i = threadIdx.x; i < 8 * 64; i += TPB) {
        int a = i >> 6, c = i & 63;
        sWea[i] = w11[c * 40 + 32 + a];
    }
    for (int i = threadIdx.x; i < 32 * 64; i += TPB) sW12[i] = w12[i];
    if (threadIdx.x < 32) sB12[threadIdx.x] = b12[threadIdx.x];
    __syncthreads();

    int n = blockIdx.x * TPB + threadIdx.x;
    if (n >= N) return;

    float aggr[32];
#pragma unroll
    for (int k = 0; k < 32; k++) aggr[k] = -3.0e38f;

    for (int j = 0; j < DEG; j++) {
        int e = n * DEG + j;
        int s = g_src[e];

        const float4* ep = (const float4*)(eattr + (size_t)e * 8);
        float4 ev0 = ep[0], ev1 = ep[1];
        float ea[8] = {ev0.x, ev0.y, ev0.z, ev0.w, ev1.x, ev1.y, ev1.z, ev1.w};

        float h[64];
        const float4* gp = (const float4*)(g_xw1 + (size_t)s * 64);
#pragma unroll
        for (int t = 0; t < 16; t++) {
            float4 v = gp[t];
            h[4*t+0] = v.x; h[4*t+1] = v.y; h[4*t+2] = v.z; h[4*t+3] = v.w;
        }
#pragma unroll
        for (int a = 0; a < 8; a++) {
            float evv = ea[a];
            const float4* wp = (const float4*)(sWea + a * 64);
#pragma unroll
            for (int t = 0; t < 16; t++) {
                float4 w = wp[t];
                h[4*t+0] += evv * w.x;
                h[4*t+1] += evv * w.y;
                h[4*t+2] += evv * w.z;
                h[4*t+3] += evv * w.w;
            }
        }
#pragma unroll
        for (int i = 0; i < 64; i++) h[i] = relu_(h[i]);

        for (int k = 0; k < 32; k += 4) {
            float a0 = sB12[k+0], a1 = sB12[k+1], a2 = sB12[k+2], a3 = sB12[k+3];
            const float4* w0 = (const float4*)(sW12 + (k+0) * 64);
            const float4* w1 = (const float4*)(sW12 + (k+1) * 64);
            const float4* w2 = (const float4*)(sW12 + (k+2) * 64);
            const float4* w3 = (const float4*)(sW12 + (k+3) * 64);
#pragma unroll
            for (int t = 0; t < 16; t++) {
                float h0 = h[4*t+0], h1 = h[4*t+1], h2 = h[4*t+2], h3 = h[4*t+3];
                float4 p;
                p = w0[t]; a0 += h0*p.x + h1*p.y + h2*p.z + h3*p.w;
                p = w1[t]; a1 += h0*p.x + h1*p.y + h2*p.z + h3*p.w;
                p = w2[t]; a2 += h0*p.x + h1*p.y + h2*p.z + h3*p.w;
                p = w3[t]; a3 += h0*p.x + h1*p.y + h2*p.z + h3*p.w;
            }
            aggr[k+0] = fmaxf(aggr[k+0], relu_(a0));
            aggr[k+1] = fmaxf(aggr[k+1], relu_(a1));
            aggr[k+2] = fmaxf(aggr[k+2], relu_(a2));
            aggr[k+3] = fmaxf(aggr[k+3], relu_(a3));
        }
    }

    float4* op = (float4*)(g_aggr + (size_t)n * 32);
#pragma unroll
    for (int t = 0; t < 8; t++)
        op[t] = make_float4(aggr[4*t+0], aggr[4*t+1], aggr[4*t+2], aggr[4*t+3]);
}

// ---------------------------------------------------------------------------
// Kernel 3: node update. u = concat(x[n], aggr[n]) (64)
// h2 = relu(u @ w2_1^T + b2_1) (64); c = relu(h2 @ w2_2^T + b2_2) (16)
// c /= max(1, ||c||); out[n] = concat(c, x[n][:16])
// FUSED: if write_xw1 != 0, also emit g_xw1[n] for the NEXT iteration from
// the freshly computed feature row (still in registers).
// ---------------------------------------------------------------------------
__global__ __launch_bounds__(TPB, 3) void k_update(const float* __restrict__ xin,
                                                   const float* __restrict__ w21,
                                                   const float* __restrict__ b21,
                                                   const float* __restrict__ w22,
                                                   const float* __restrict__ b22,
                                                   const float* __restrict__ w11,
                                                   const float* __restrict__ b11,
                                                   float* __restrict__ xout,
                                                   int N, int write_xw1) {
    __shared__ __align__(16) float sW21[64 * 64];
    __shared__ __align__(16) float sW22[16 * 64];
    __shared__ __align__(16) float sW11[64 * 40];
    __shared__ float sB21[64];
    __shared__ float sB22[16];
    __shared__ float sB11[64];
    for (int i = threadIdx.x; i < 64 * 64; i += TPB) sW21[i] = w21[i];
    for (int i = threadIdx.x; i < 16 * 64; i += TPB) sW22[i] = w22[i];
    for (int i = threadIdx.x; i < 64 * 40; i += TPB) sW11[i] = w11[i];
    if (threadIdx.x < 64) sB21[threadIdx.x] = b21[threadIdx.x];
    if (threadIdx.x < 16) sB22[threadIdx.x] = b22[threadIdx.x];
    if (threadIdx.x < 64) sB11[threadIdx.x] = b11[threadIdx.x];
    __syncthreads();

    int n = blockIdx.x * TPB + threadIdx.x;
    if (n >= N) return;

    float u[64];
    const float4* xp = (const float4*)(xin + (size_t)n * 32);
    const float4* ap = (const float4*)(g_aggr + (size_t)n * 32);
#pragma unroll
    for (int t = 0; t < 8; t++) {
        float4 v = xp[t];
        u[4*t+0] = v.x; u[4*t+1] = v.y; u[4*t+2] = v.z; u[4*t+3] = v.w;
    }
#pragma unroll
    for (int t = 0; t < 8; t++) {
        float4 v = ap[t];
        u[32+4*t+0] = v.x; u[32+4*t+1] = v.y; u[32+4*t+2] = v.z; u[32+4*t+3] = v.w;
    }

    float h2[64];
    for (int j = 0; j < 64; j += 4) {
        float a0 = sB21[j+0], a1 = sB21[j+1], a2 = sB21[j+2], a3 = sB21[j+3];
        const float4* w0 = (const float4*)(sW21 + (j+0) * 64);
        const float4* w1 = (const float4*)(sW21 + (j+1) * 64);
        const float4* w2 = (const float4*)(sW21 + (j+2) * 64);
        const float4* w3 = (const float4*)(sW21 + (j+3) * 64);
#pragma unroll
        for (int t = 0; t < 16; t++) {
            float h0 = u[4*t+0], h1 = u[4*t+1], hh2 = u[4*t+2], h3 = u[4*t+3];
            float4 p;
            p = w0[t]; a0 += h0*p.x + h1*p.y + hh2*p.z + h3*p.w;
            p = w1[t]; a1 += h0*p.x + h1*p.y + hh2*p.z + h3*p.w;
            p = w2[t]; a2 += h0*p.x + h1*p.y + hh2*p.z + h3*p.w;
            p = w3[t]; a3 += h0*p.x + h1*p.y + hh2*p.z + h3*p.w;
        }
        h2[j+0] = relu_(a0); h2[j+1] = relu_(a1);
        h2[j+2] = relu_(a2); h2[j+3] = relu_(a3);
    }

    float c[16];
    for (int k = 0; k < 16; k += 4) {
        float a0 = sB22[k+0], a1 = sB22[k+1], a2 = sB22[k+2], a3 = sB22[k+3];
        const float4* w0 = (const float4*)(sW22 + (k+0) * 64);
        const float4* w1 = (const float4*)(sW22 + (k+1) * 64);
        const float4* w2 = (const float4*)(sW22 + (k+2) * 64);
        const float4* w3 = (const float4*)(sW22 + (k+3) * 64);
#pragma unroll
        for (int t = 0; t < 16; t++) {
            float h0 = h2[4*t+0], h1 = h2[4*t+1], hh2 = h2[4*t+2], h3 = h2[4*t+3];
            float4 p;
            p = w0[t]; a0 += h0*p.x + h1*p.y + hh2*p.z + h3*p.w;
            p = w1[t]; a1 += h0*p.x + h1*p.y + hh2*p.z + h3*p.w;
            p = w2[t]; a2 += h0*p.x + h1*p.y + hh2*p.z + h3*p.w;
            p = w3[t]; a3 += h0*p.x + h1*p.y + hh2*p.z + h3*p.w;
        }
        c[k+0] = relu_(a0); c[k+1] = relu_(a1);
        c[k+2] = relu_(a2); c[k+3] = relu_(a3);
    }

    float ss = 0.0f;
#pragma unroll
    for (int k = 0; k < 16; k++) ss += c[k] * c[k];
    float d = fmaxf(1.0f, sqrtf(ss));
    float inv = 1.0f / d;

    // New feature row for next iteration: xr = [c*inv (16) | old x[:16] (16)]
    float xr[32];
#pragma unroll
    for (int k = 0; k < 16; k++) xr[k] = c[k] * inv;
#pragma unroll
    for (int k = 0; k < 16; k++) xr[16 + k] = u[k];

    float4* op = (float4*)(xout + (size_t)n * 32);
#pragma unroll
    for (int t = 0; t < 8; t++)
        op[t] = make_float4(xr[4*t+0], xr[4*t+1], xr[4*t+2], xr[4*t+3]);

    if (write_xw1) {
        float4* xwp = (float4*)(g_xw1 + (size_t)n * 64);
        for (int j = 0; j < 64; j += 4) {
            float a0 = sB11[j+0], a1 = sB11[j+1], a2 = sB11[j+2], a3 = sB11[j+3];
            const float4* w0 = (const float4*)(sW11 + (j+0) * 40);
            const float4* w1 = (const float4*)(sW11 + (j+1) * 40);
            const float4* w2 = (const float4*)(sW11 + (j+2) * 40);
            const float4* w3 = (const float4*)(sW11 + (j+3) * 40);
#pragma unroll
            for (int t = 0; t < 8; t++) {
                float h0 = xr[4*t+0], h1 = xr[4*t+1], hh2 = xr[4*t+2], h3 = xr[4*t+3];
                float4 p;
                p = w0[t]; a0 += h0*p.x + h1*p.y + hh2*p.z + h3*p.w;
                p = w1[t]; a1 += h0*p.x + h1*p.y + hh2*p.z + h3*p.w;
                p = w2[t]; a2 += h0*p.x + h1*p.y + hh2*p.z + h3*p.w;
                p = w3[t]; a3 += h0*p.x + h1*p.y + hh2*p.z + h3*p.w;
            }
            xwp[j >> 2] = make_float4(a0, a1, a2, a3);
        }
    }
}

// ---------------------------------------------------------------------------
extern "C" void kernel_launch(void* const* d_in, const int* in_sizes, int n_in,
                              void* d_out, int out_size) {
    const float* x   = (const float*)d_in[0];
    const int*   ei  = (const int*)d_in[1];   // [2, E]; int32 or int64 (normalized on device)
    const float* ea  = (const float*)d_in[2];
    const float* w11 = (const float*)d_in[3];
    const float* b11 = (const float*)d_in[4];
    const float* w12 = (const float*)d_in[5];
    const float* b12 = (const float*)d_in[6];
    const float* w21 = (const float*)d_in[7];
    const float* b21 = (const float*)d_in[8];
    const float* w22 = (const float*)d_in[9];
    const float* b22 = (const float*)d_in[10];

    int N = in_sizes[0] / 32;
    int E = N * DEG;
    float* pA = nullptr;
    float* pB = nullptr;
    cudaGetSymbolAddress((void**)&pA, g_bufA);
    cudaGetSymbolAddress((void**)&pB, g_bufB);
    float* fout = (float*)d_out;

    int blocks  = (N + TPB - 1) / TPB;
    int eblocks = (E + TPB - 1) / TPB;

    // Normalize src indices to int32 (handles int32 or int64 edge_index).
    k_convert<<<eblocks, TPB>>>(ei, E);

    // Iteration 0: xw1 from original x, then edge + update (update emits xw1 for it1)
    k_xw1<<<blocks, TPB>>>(x, w11, b11, N);
    k_edge<<<blocks, TPB>>>(ea, w11, w12, b12, N);
    k_update<<<blocks, TPB>>>(x, w21, b21, w22, b22, w11, b11, pA, N, 1);

    // Iteration 1
    k_edge<<<blocks, TPB>>>(ea, w11, w12, b12, N);
    k_update<<<blocks, TPB>>>(pA, w21, b21, w22, b22, w11, b11, pB, N, 1);

    // Iteration 2 (final): no xw1 needed
    k_edge<<<blocks, TPB>>>(ea, w11, w12, b12, N);
    k_update<<<blocks, TPB>>>(pB, w21, b21, w22, b22, w11, b11, fout, N, 0);
}

// round 9
// speedup vs baseline: 1.6378x; 1.6378x over previous
#include <cuda_runtime.h>

#define NN   100000
#define DEG  16
#define EE   (NN * DEG)
#define TPB  128

typedef unsigned long long ull;

// Scratch (no allocations allowed): ping-pong node features, per-node xW1, aggregates.
__device__ float g_bufA[(size_t)NN * 32];
__device__ float g_bufB[(size_t)NN * 32];
__device__ float g_xw1[(size_t)NN * 64];
__device__ float g_aggr[(size_t)NN * 32];
__device__ int   g_src[(size_t)EE];

__device__ __forceinline__ float relu_(float v) { return fmaxf(v, 0.0f); }

// ---- packed f32x2 helpers (sm_103a) ---------------------------------------
__device__ __forceinline__ ull pk2(float a, float b) {
    ull r; asm("mov.b64 %0, {%1, %2};" : "=l"(r) : "f"(a), "f"(b)); return r;
}
__device__ __forceinline__ void upk2(ull v, float& a, float& b) {
    asm("mov.b64 {%0, %1}, %2;" : "=f"(a), "=f"(b) : "l"(v));
}
__device__ __forceinline__ ull fma2_(ull a, ull b, ull c) {
    ull d; asm("fma.rn.f32x2 %0, %1, %2, %3;" : "=l"(d) : "l"(a), "l"(b), "l"(c)); return d;
}

// ---------------------------------------------------------------------------
// Kernel 0: normalize edge_index row 0 (src) to int32 (int32 or int64 input).
// ---------------------------------------------------------------------------
__global__ __launch_bounds__(TPB) void k_convert(const int* __restrict__ ei_raw, int E) {
    __shared__ int s_is64;
    if (threadIdx.x == 0) {
        int allz = 1;
        for (int k = 0; k < 64; k++) allz &= (ei_raw[2 * k + 1] == 0);
        s_is64 = allz;
    }
    __syncthreads();
    int is64 = s_is64;
    int e = blockIdx.x * TPB + threadIdx.x;
    if (e < E) g_src[e] = is64 ? ei_raw[2 * e] : ei_raw[e];
}

// ---------------------------------------------------------------------------
// Kernel 1: g_xw1[n] = b1_1 + x[n] @ w1_1[:, :32]^T  (first iteration only)
// ---------------------------------------------------------------------------
__global__ __launch_bounds__(TPB) void k_xw1(const float* __restrict__ x,
                                             const float* __restrict__ w11,
                                             const float* __restrict__ b11,
                                             int N) {
    __shared__ __align__(16) float sW[64 * 40];
    __shared__ float sB[64];
    for (int i = threadIdx.x; i < 64 * 40; i += TPB) sW[i] = w11[i];
    if (threadIdx.x < 64) sB[threadIdx.x] = b11[threadIdx.x];
    __syncthreads();

    int n = blockIdx.x * TPB + threadIdx.x;
    if (n >= N) return;

    float xr[32];
    const float4* xp = (const float4*)(x + (size_t)n * 32);
#pragma unroll
    for (int t = 0; t < 8; t++) {
        float4 v = xp[t];
        xr[4*t+0] = v.x; xr[4*t+1] = v.y; xr[4*t+2] = v.z; xr[4*t+3] = v.w;
    }

    float4* op = (float4*)(g_xw1 + (size_t)n * 64);
    for (int j = 0; j < 64; j += 4) {
        float a0 = sB[j+0], a1 = sB[j+1], a2 = sB[j+2], a3 = sB[j+3];
        const float4* w0 = (const float4*)(sW + (j+0) * 40);
        const float4* w1 = (const float4*)(sW + (j+1) * 40);
        const float4* w2 = (const float4*)(sW + (j+2) * 40);
        const float4* w3 = (const float4*)(sW + (j+3) * 40);
#pragma unroll
        for (int t = 0; t < 8; t++) {
            float h0 = xr[4*t+0], h1 = xr[4*t+1], h2 = xr[4*t+2], h3 = xr[4*t+3];
            float4 p;
            p = w0[t]; a0 += h0*p.x + h1*p.y + h2*p.z + h3*p.w;
            p = w1[t]; a1 += h0*p.x + h1*p.y + h2*p.z + h3*p.w;
            p = w2[t]; a2 += h0*p.x + h1*p.y + h2*p.z + h3*p.w;
            p = w3[t]; a3 += h0*p.x + h1*p.y + h2*p.z + h3*p.w;
        }
        op[j >> 2] = make_float4(a0, a1, a2, a3);
    }
}

// ---------------------------------------------------------------------------
// Kernel 2: per-node edge MLP + max aggregation, packed f32x2 math.
//   h[i]   = relu(xw1[src][i] + sum_a ea[a]*Wea[a][i])         (64)
//   msg[k] = relu(b12[k] + sum_i h[i]*W12[k][i])               (32)
//   aggr[n][k] = max_j msg  (16 edges; msg >= 0 so init 0 is exact)
// Output pairs packed: acc2[m] = (msg[2m], msg[2m+1]); h streamed per quad.
// ---------------------------------------------------------------------------
__global__ __launch_bounds__(TPB, 4) void k_edge(const float* __restrict__ eattr,
                                                 const float* __restrict__ w11,
                                                 const float* __restrict__ w12,
                                                 const float* __restrict__ b12,
                                                 int N) {
    __shared__ __align__(16) float sWea[8 * 64];    // [a][i] = w11[i*40 + 32 + a]
    __shared__ __align__(16) float sW12c[64 * 32];  // float2 entry (i*16+m) = (W12[2m][i], W12[2m+1][i])
    __shared__ __align__(16) float sB12[32];
    for (int i = threadIdx.x; i < 8 * 64; i += TPB) {
        int a = i >> 6, c = i & 63;
        sWea[i] = w11[c * 40 + 32 + a];
    }
    for (int e = threadIdx.x; e < 64 * 16; e += TPB) {
        int i = e >> 4, m = e & 15;
        sW12c[2 * e + 0] = w12[(2 * m + 0) * 64 + i];
        sW12c[2 * e + 1] = w12[(2 * m + 1) * 64 + i];
    }
    if (threadIdx.x < 32) sB12[threadIdx.x] = b12[threadIdx.x];
    __syncthreads();

    int n = blockIdx.x * TPB + threadIdx.x;
    if (n >= N) return;

    const ull* sBu = (const ull*)sB12;                    // 16 packed bias pairs
    const ulonglong2* sWeaU = (const ulonglong2*)sWea;    // (a*16 + q)
    const ulonglong2* sW12U = (const ulonglong2*)sW12c;   // (i*8 + mm)

    float aggr[32];
#pragma unroll
    for (int k = 0; k < 32; k++) aggr[k] = 0.0f;          // msg >= 0 (relu)

    for (int j = 0; j < DEG; j++) {
        int e = n * DEG + j;
        int s = g_src[e];

        const float4* ep = (const float4*)(eattr + (size_t)e * 8);
        float4 ev0 = ep[0], ev1 = ep[1];
        ull ea2[8];
        ea2[0] = pk2(ev0.x, ev0.x); ea2[1] = pk2(ev0.y, ev0.y);
        ea2[2] = pk2(ev0.z, ev0.z); ea2[3] = pk2(ev0.w, ev0.w);
        ea2[4] = pk2(ev1.x, ev1.x); ea2[5] = pk2(ev1.y, ev1.y);
        ea2[6] = pk2(ev1.z, ev1.z); ea2[7] = pk2(ev1.w, ev1.w);

        ull acc[16];
#pragma unroll
        for (int m = 0; m < 16; m++) acc[m] = sBu[m];

        const ulonglong2* gp = (const ulonglong2*)(g_xw1 + (size_t)s * 64);  // 16 quads

#pragma unroll 4
        for (int q = 0; q < 16; q++) {
            // ---- layer 1 for quad i = 4q .. 4q+3 (2 packed pairs) ----
            ulonglong2 xv = gp[q];
            ull h2a = xv.x, h2b = xv.y;
#pragma unroll
            for (int a = 0; a < 8; a++) {
                ulonglong2 wv = sWeaU[a * 16 + q];
                h2a = fma2_(ea2[a], wv.x, h2a);
                h2b = fma2_(ea2[a], wv.y, h2b);
            }
            float h0, h1, h2, h3;
            upk2(h2a, h0, h1); upk2(h2b, h2, h3);
            h0 = relu_(h0); h1 = relu_(h1); h2 = relu_(h2); h3 = relu_(h3);
            ull hh[4] = { pk2(h0, h0), pk2(h1, h1), pk2(h2, h2), pk2(h3, h3) };

            // ---- layer 2: scatter quad into 16 packed accumulators ----
            const ulonglong2* wc = sW12U + (size_t)(4 * q) * 8;
#pragma unroll
            for (int t = 0; t < 4; t++) {
#pragma unroll
                for (int mm = 0; mm < 8; mm++) {
                    ulonglong2 wv = wc[t * 8 + mm];
                    acc[2 * mm + 0] = fma2_(hh[t], wv.x, acc[2 * mm + 0]);
                    acc[2 * mm + 1] = fma2_(hh[t], wv.y, acc[2 * mm + 1]);
                }
            }
        }

        // ---- relu + running max ----
#pragma unroll
        for (int m = 0; m < 16; m++) {
            float m0, m1;
            upk2(acc[m], m0, m1);
            aggr[2 * m + 0] = fmaxf(aggr[2 * m + 0], relu_(m0));
            aggr[2 * m + 1] = fmaxf(aggr[2 * m + 1], relu_(m1));
        }
    }

    float4* op = (float4*)(g_aggr + (size_t)n * 32);
#pragma unroll
    for (int t = 0; t < 8; t++)
        op[t] = make_float4(aggr[4*t+0], aggr[4*t+1], aggr[4*t+2], aggr[4*t+3]);
}

// ---------------------------------------------------------------------------
// Kernel 3: node update (+ fused xw1 emit for the next iteration).
// ---------------------------------------------------------------------------
__global__ __launch_bounds__(TPB, 3) void k_update(const float* __restrict__ xin,
                                                   const float* __restrict__ w21,
                                                   const float* __restrict__ b21,
                                                   const float* __restrict__ w22,
                                                   const float* __restrict__ b22,
                                                   const float* __restrict__ w11,
                                                   const float* __restrict__ b11,
                                                   float* __restrict__ xout,
                                                   int N, int write_xw1) {
    __shared__ __align__(16) float sW21[64 * 64];
    __shared__ __align__(16) float sW22[16 * 64];
    __shared__ __align__(16) float sW11[64 * 40];
    __shared__ float sB21[64];
    __shared__ float sB22[16];
    __shared__ float sB11[64];
    for (int i = threadIdx.x; i < 64 * 64; i += TPB) sW21[i] = w21[i];
    for (int i = threadIdx.x; i < 16 * 64; i += TPB) sW22[i] = w22[i];
    for (int i = threadIdx.x; i < 64 * 40; i += TPB) sW11[i] = w11[i];
    if (threadIdx.x < 64) sB21[threadIdx.x] = b21[threadIdx.x];
    if (threadIdx.x < 16) sB22[threadIdx.x] = b22[threadIdx.x];
    if (threadIdx.x < 64) sB11[threadIdx.x] = b11[threadIdx.x];
    __syncthreads();

    int n = blockIdx.x * TPB + threadIdx.x;
    if (n >= N) return;

    float u[64];
    const float4* xp = (const float4*)(xin + (size_t)n * 32);
    const float4* ap = (const float4*)(g_aggr + (size_t)n * 32);
#pragma unroll
    for (int t = 0; t < 8; t++) {
        float4 v = xp[t];
        u[4*t+0] = v.x; u[4*t+1] = v.y; u[4*t+2] = v.z; u[4*t+3] = v.w;
    }
#pragma unroll
    for (int t = 0; t < 8; t++) {
        float4 v = ap[t];
        u[32+4*t+0] = v.x; u[32+4*t+1] = v.y; u[32+4*t+2] = v.z; u[32+4*t+3] = v.w;
    }

    float h2[64];
    for (int j = 0; j < 64; j += 4) {
        float a0 = sB21[j+0], a1 = sB21[j+1], a2 = sB21[j+2], a3 = sB21[j+3];
        const float4* w0 = (const float4*)(sW21 + (j+0) * 64);
        const float4* w1 = (const float4*)(sW21 + (j+1) * 64);
        const float4* w2 = (const float4*)(sW21 + (j+2) * 64);
        const float4* w3 = (const float4*)(sW21 + (j+3) * 64);
#pragma unroll
        for (int t = 0; t < 16; t++) {
            float h0 = u[4*t+0], h1 = u[4*t+1], hh2 = u[4*t+2], h3 = u[4*t+3];
            float4 p;
            p = w0[t]; a0 += h0*p.x + h1*p.y + hh2*p.z + h3*p.w;
            p = w1[t]; a1 += h0*p.x + h1*p.y + hh2*p.z + h3*p.w;
            p = w2[t]; a2 += h0*p.x + h1*p.y + hh2*p.z + h3*p.w;
            p = w3[t]; a3 += h0*p.x + h1*p.y + hh2*p.z + h3*p.w;
        }
        h2[j+0] = relu_(a0); h2[j+1] = relu_(a1);
        h2[j+2] = relu_(a2); h2[j+3] = relu_(a3);
    }

    float c[16];
    for (int k = 0; k < 16; k += 4) {
        float a0 = sB22[k+0], a1 = sB22[k+1], a2 = sB22[k+2], a3 = sB22[k+3];
        const float4* w0 = (const float4*)(sW22 + (k+0) * 64);
        const float4* w1 = (const float4*)(sW22 + (k+1) * 64);
        const float4* w2 = (const float4*)(sW22 + (k+2) * 64);
        const float4* w3 = (const float4*)(sW22 + (k+3) * 64);
#pragma unroll
        for (int t = 0; t < 16; t++) {
            float h0 = h2[4*t+0], h1 = h2[4*t+1], hh2 = h2[4*t+2], h3 = h2[4*t+3];
            float4 p;
            p = w0[t]; a0 += h0*p.x + h1*p.y + hh2*p.z + h3*p.w;
            p = w1[t]; a1 += h0*p.x + h1*p.y + hh2*p.z + h3*p.w;
            p = w2[t]; a2 += h0*p.x + h1*p.y + hh2*p.z + h3*p.w;
            p = w3[t]; a3 += h0*p.x + h1*p.y + hh2*p.z + h3*p.w;
        }
        c[k+0] = relu_(a0); c[k+1] = relu_(a1);
        c[k+2] = relu_(a2); c[k+3] = relu_(a3);
    }

    float ss = 0.0f;
#pragma unroll
    for (int k = 0; k < 16; k++) ss += c[k] * c[k];
    float d = fmaxf(1.0f, sqrtf(ss));
    float inv = 1.0f / d;

    float xr[32];
#pragma unroll
    for (int k = 0; k < 16; k++) xr[k] = c[k] * inv;
#pragma unroll
    for (int k = 0; k < 16; k++) xr[16 + k] = u[k];

    float4* op = (float4*)(xout + (size_t)n * 32);
#pragma unroll
    for (int t = 0; t < 8; t++)
        op[t] = make_float4(xr[4*t+0], xr[4*t+1], xr[4*t+2], xr[4*t+3]);

    if (write_xw1) {
        float4* xwp = (float4*)(g_xw1 + (size_t)n * 64);
        for (int j = 0; j < 64; j += 4) {
            float a0 = sB11[j+0], a1 = sB11[j+1], a2 = sB11[j+2], a3 = sB11[j+3];
            const float4* w0 = (const float4*)(sW11 + (j+0) * 40);
            const float4* w1 = (const float4*)(sW11 + (j+1) * 40);
            const float4* w2 = (const float4*)(sW11 + (j+2) * 40);
            const float4* w3 = (const float4*)(sW11 + (j+3) * 40);
#pragma unroll
            for (int t = 0; t < 8; t++) {
                float h0 = xr[4*t+0], h1 = xr[4*t+1], hh2 = xr[4*t+2], h3 = xr[4*t+3];
                float4 p;
                p = w0[t]; a0 += h0*p.x + h1*p.y + hh2*p.z + h3*p.w;
                p = w1[t]; a1 += h0*p.x + h1*p.y + hh2*p.z + h3*p.w;
                p = w2[t]; a2 += h0*p.x + h1*p.y + hh2*p.z + h3*p.w;
                p = w3[t]; a3 += h0*p.x + h1*p.y + hh2*p.z + h3*p.w;
            }
            xwp[j >> 2] = make_float4(a0, a1, a2, a3);
        }
    }
}

// ---------------------------------------------------------------------------
extern "C" void kernel_launch(void* const* d_in, const int* in_sizes, int n_in,
                              void* d_out, int out_size) {
    const float* x   = (const float*)d_in[0];
    const int*   ei  = (const int*)d_in[1];   // [2, E]; int32 or int64 (normalized on device)
    const float* ea  = (const float*)d_in[2];
    const float* w11 = (const float*)d_in[3];
    const float* b11 = (const float*)d_in[4];
    const float* w12 = (const float*)d_in[5];
    const float* b12 = (const float*)d_in[6];
    const float* w21 = (const float*)d_in[7];
    const float* b21 = (const float*)d_in[8];
    const float* w22 = (const float*)d_in[9];
    const float* b22 = (const float*)d_in[10];

    int N = in_sizes[0] / 32;
    int E = N * DEG;
    float* pA = nullptr;
    float* pB = nullptr;
    cudaGetSymbolAddress((void**)&pA, g_bufA);
    cudaGetSymbolAddress((void**)&pB, g_bufB);
    float* fout = (float*)d_out;

    int blocks  = (N + TPB - 1) / TPB;
    int eblocks = (E + TPB - 1) / TPB;

    k_convert<<<eblocks, TPB>>>(ei, E);

    // Iteration 0
    k_xw1<<<blocks, TPB>>>(x, w11, b11, N);
    k_edge<<<blocks, TPB>>>(ea, w11, w12, b12, N);
    k_update<<<blocks, TPB>>>(x, w21, b21, w22, b22, w11, b11, pA, N, 1);

    // Iteration 1
    k_edge<<<blocks, TPB>>>(ea, w11, w12, b12, N);
    k_update<<<blocks, TPB>>>(pA, w21, b21, w22, b22, w11, b11, pB, N, 1);

    // Iteration 2 (final)
    k_edge<<<blocks, TPB>>>(ea, w11, w12, b12, N);
    k_update<<<blocks, TPB>>>(pB, w21, b21, w22, b22, w11, b11, fout, N, 0);
}